// round 1
// baseline (speedup 1.0000x reference)
#include <cuda_runtime.h>

// Problem: T=11, H=W=2048. Inputs: output (u) and f1, each [11,1,2048,2048] f32.
// Outputs: 2 scalars (phy, bc).

#define HH 2048
#define WI 2048
static const size_t HWs = (size_t)HH * (size_t)WI;

static __device__ double g_phy;
static __device__ double g_bc;

// ---- fractional-derivative matrix, closed form ----
// M[i,i]=1, M[i,0]=-w[i-1], M[i,k]=-(w[i-k-1]-w[i-k]) for 1<=k<i, all * pref.
// pref = 0.1^{-0.5} / Gamma(1.5) = sqrt(10) * 2/sqrt(pi)
constexpr double PREFD = 3.5682482323055424;
constexpr double WQ[10] = {
    1.0,
    0.41421356237309515,  // sqrt2-1
    0.31783724519578215,  // sqrt3-sqrt2
    0.26794919243112270,  // 2-sqrt3
    0.23606797749978969,  // sqrt5-2
    0.21342176528338802,  // sqrt6-sqrt5
    0.19626156828141264,  // sqrt7-sqrt6
    0.18267581368159972,  // sqrt8-sqrt7
    0.17157287525380971,  // 3-sqrt8
    0.16227766016837933   // sqrt10-3
};

__global__ void init_kernel() { g_phy = 0.0; g_bc = 0.0; }

__device__ __forceinline__ void block_reduce_add(double v, double* target,
                                                 int tid, int nthreads) {
    #pragma unroll
    for (int o = 16; o > 0; o >>= 1)
        v += __shfl_down_sync(0xffffffffu, v, o);
    __shared__ double sr[32];
    int lane = tid & 31, wid = tid >> 5;
    if (lane == 0) sr[wid] = v;
    __syncthreads();
    int nw = (nthreads + 31) >> 5;
    if (wid == 0) {
        v = (lane < nw) ? sr[lane] : 0.0;
        #pragma unroll
        for (int o = 16; o > 0; o >>= 1)
            v += __shfl_down_sync(0xffffffffu, v, o);
        if (lane == 0) atomicAdd(target, v);
    }
}

// Main fused kernel: each thread handles 4 consecutive pixels (float4-aligned)
// for all 11 time slices. Interior rows h in [1,2046]; w boundary masked.
__global__ __launch_bounds__(256) void phy_kernel(const float* __restrict__ u,
                                                  const float* __restrict__ f1) {
    const int tx = threadIdx.x, ty = threadIdx.y;
    const int w0 = 4 * (blockIdx.x * 16 + tx);       // 0..2044, 16B aligned
    const int h  = 1 + blockIdx.y * 16 + ty;         // 1..2048 (mask > 2046)

    float acc = 0.0f;

    if (h <= HH - 2) {
        const float A = 0.34520446044393f;
        const float B = 0.309591078922457f;
        const float C = -2.619182157203629f;
        const float KLAP = 0.01f * 4194304.0f;       // kappa / DX^2

        const float fPW[10] = {
            (float)(PREFD * WQ[0]), (float)(PREFD * WQ[1]), (float)(PREFD * WQ[2]),
            (float)(PREFD * WQ[3]), (float)(PREFD * WQ[4]), (float)(PREFD * WQ[5]),
            (float)(PREFD * WQ[6]), (float)(PREFD * WQ[7]), (float)(PREFD * WQ[8]),
            (float)(PREFD * WQ[9])
        };
        const float fPD[10] = {
            0.0f,
            (float)(PREFD * (WQ[0] - WQ[1])), (float)(PREFD * (WQ[1] - WQ[2])),
            (float)(PREFD * (WQ[2] - WQ[3])), (float)(PREFD * (WQ[3] - WQ[4])),
            (float)(PREFD * (WQ[4] - WQ[5])), (float)(PREFD * (WQ[5] - WQ[6])),
            (float)(PREFD * (WQ[6] - WQ[7])), (float)(PREFD * (WQ[7] - WQ[8])),
            (float)(PREFD * (WQ[8] - WQ[9]))
        };
        const float PREFF = (float)PREFD;

        const int offL = (w0 == 0)        ? 0 : -1;
        const int offR = (w0 == WI - 4)   ? 3 : 4;
        const float msk[4] = { (w0 == 0) ? 0.0f : 1.0f, 1.0f, 1.0f,
                               (w0 == WI - 4) ? 0.0f : 1.0f };

        float uc[11][4];  // center u values across time, per pixel
        const size_t base = (size_t)(h - 1) * WI + (size_t)w0;

        #pragma unroll
        for (int t = 0; t < 11; t++) {
            const float* pt = u + (size_t)t * HWs + base;  // row h-1
            const float* pm = pt + WI;                      // row h
            const float* pb = pm + WI;                      // row h+1
            const float4 t4 = *(const float4*)pt;
            const float  tl = pt[offL], tr = pt[offR];
            const float4 m4 = *(const float4*)pm;
            const float  ml = pm[offL], mr = pm[offR];
            const float4 b4 = *(const float4*)pb;
            const float  bl = pb[offL], br = pb[offR];
            const float4 f4 = *(const float4*)(f1 + (size_t)t * HWs + base + WI);

            const float tc[6] = { tl, t4.x, t4.y, t4.z, t4.w, tr };
            const float mc[6] = { ml, m4.x, m4.y, m4.z, m4.w, mr };
            const float bb[6] = { bl, b4.x, b4.y, b4.z, b4.w, br };
            const float ff[4] = { f4.x, f4.y, f4.z, f4.w };

            #pragma unroll
            for (int j = 0; j < 4; j++) {
                const float center = mc[j + 1];
                float conv = A * (tc[j] + tc[j + 2] + bb[j] + bb[j + 2])
                           + B * (tc[j + 1] + bb[j + 1] + mc[j] + mc[j + 2])
                           + C * center;
                float fu = center - ff[j] - KLAP * conv;
                if (t > 0) {
                    float Dv = PREFF * center - fPW[t - 1] * uc[0][j];
                    #pragma unroll
                    for (int k = 1; k < t; k++)
                        Dv -= fPD[t - k] * uc[k][j];
                    fu += Dv;
                }
                fu *= msk[j];
                acc += fu * fu;
                uc[t][j] = center;
            }
        }
    }

    const int tid = ty * 16 + tx;
    block_reduce_add((double)acc, &g_phy, tid, 256);
}

// Boundary-condition loss: 10 time slices x 2048 boundary positions.
__global__ __launch_bounds__(256) void bc_kernel(const float* __restrict__ u) {
    const int it = blockIdx.x;                         // 0..9 -> time slice it+1
    const int j  = blockIdx.y * 256 + threadIdx.x;     // 0..2047

    const float* ut = u + (size_t)(it + 1) * HWs;
    const float tval = 0.1f + 0.1f * (float)it;        // linspace(0.1,1.0,10)
    const float tt = powf(tval, 1.5f);
    const float xj = (float)j * (1.0f / 2047.0f);      // linspace(0,1,2048)
    const float x1b = tt * sinf(6.2831853071795862f * xj);

    const float l  = ut[(size_t)j * WI];
    const float r  = ut[(size_t)j * WI + (WI - 1)];
    const float tp = ut[j];
    const float bt = ut[(size_t)(HH - 1) * WI + j];

    const float dl = l - x1b, dr = r - x1b, du = tp - x1b, db = bt - x1b;
    const double v = (double)(dl * dl + dr * dr + du * du + db * db);

    block_reduce_add(v, &g_bc, threadIdx.x, 256);
}

__global__ void final_kernel(float* out) {
    // phy = 2 * sum / (11 * 2046 * 2046)
    out[0] = (float)(2.0 * g_phy / 46047276.0);
    // bc = sum / (10*2048) / 2048
    out[1] = (float)(g_bc / 41943040.0);
}

extern "C" void kernel_launch(void* const* d_in, const int* in_sizes, int n_in,
                              void* d_out, int out_size) {
    const float* u  = (const float*)d_in[0];
    const float* f1 = (const float*)d_in[1];
    float* out = (float*)d_out;

    init_kernel<<<1, 1>>>();

    dim3 blk(16, 16);
    dim3 grd(32, 128);  // 512 x-threads (x4 pixels) x 2048 rows
    phy_kernel<<<grd, blk>>>(u, f1);

    bc_kernel<<<dim3(10, 8), 256>>>(u);

    final_kernel<<<1, 1>>>(out);
}